// round 15
// baseline (speedup 1.0000x reference)
#include <cuda_runtime.h>
#include <math.h>
#include <stdint.h>

typedef unsigned long long u64;

#define NB    64
#define HID   512
#define VOC   32000
#define TT    50
#define NBLK_B 250
#define NPART 250
#define NKS   8
#define START_TOK 1
#define END_TOK 2

// ---- kBmma smem (floats): 2 buffers of [Whi 128x36 | Wlo 128x36 | hhi 32x72 | hlo 32x72]
#define WS_TILE (128 * 36)                          // 4608
#define HS_TILE (32 * 72)                           // 2304
#define BUF_FLOATS (2 * WS_TILE + 2 * HS_TILE)      // 13824
#define BMMA_SMEM (2 * BUF_FLOATS * 4)              // 110592 bytes -> 2 blocks/SM
// ---- kGatesM smem (floats): Whi 128x72 | Wlo 128x72 | hhi 64x72 | hlo 64x72
#define GW_TILE 9216
#define GH_TILE 4608
#define GATES_SMEM ((2 * GW_TILE + 2 * GH_TILE) * 4) // 110592 bytes

// ---------------- device scratch ----------------
__device__ float g_Wh[VOC * HID];          // W_lin tf32-hi [r][k]
__device__ float g_Wlo[VOC * HID];         // W_lin tf32-lo [r][k]
__device__ float g_Wgh[2048 * 1024];       // gates W combined hi [j][k]
__device__ float g_Wgl[2048 * 1024];       // gates W combined lo
__device__ float g_aht[HID * NB];          // h tf32-hi transposed [k][b]
__device__ float g_alt[HID * NB];          // h tf32-lo transposed [k][b]
__device__ float g_c[NB * HID];
__device__ float g_gp[NKS][NB * 2048];     // split-K gate partials
__device__ int   g_word[NB];
__device__ int   g_mask[NB];
__device__ int   g_done;
__device__ float g_pv[NPART * NB];
__device__ int   g_pi[NPART * NB];

// ---------------- helpers ----------------
__device__ __forceinline__ void stcs4(float* p, float4 v) {
    asm volatile("st.global.cs.v4.f32 [%0], {%1, %2, %3, %4};"
                 :: "l"(p), "f"(v.x), "f"(v.y), "f"(v.z), "f"(v.w) : "memory");
}
__device__ __forceinline__ void tf32split(float f, float &hi, float &lo) {
    uint32_t hb, lb;
    asm("cvt.rna.tf32.f32 %0, %1;" : "=r"(hb) : "f"(f));
    hi = __uint_as_float(hb);
    float r = f - hi;
    asm("cvt.rna.tf32.f32 %0, %1;" : "=r"(lb) : "f"(r));
    lo = __uint_as_float(lb);
}
__device__ __forceinline__ void mma8(float (&d)[4], const uint32_t (&a)[4],
                                     const uint32_t (&b)[2]) {
    asm("mma.sync.aligned.m16n8k8.row.col.f32.tf32.tf32.f32 "
        "{%0,%1,%2,%3}, {%4,%5,%6,%7}, {%8,%9}, {%0,%1,%2,%3};"
        : "+f"(d[0]), "+f"(d[1]), "+f"(d[2]), "+f"(d[3])
        : "r"(a[0]), "r"(a[1]), "r"(a[2]), "r"(a[3]), "r"(b[0]), "r"(b[1]));
}
__device__ __forceinline__ uint32_t smem_u32(const void* p) {
    uint32_t a;
    asm("{ .reg .u64 t; cvta.to.shared.u64 t, %1; cvt.u32.u64 %0, t; }" : "=r"(a) : "l"(p));
    return a;
}
__device__ __forceinline__ void cpa16(uint32_t saddr, const float* g) {
    asm volatile("cp.async.ca.shared.global [%0], [%1], 16;" :: "r"(saddr), "l"(g));
}

// ---------------- once-per-replay transforms ----------------
__global__ void kSplitW(const float* __restrict__ Wl) {
    int i = blockIdx.x * 256 + threadIdx.x;
    float hi, lo;
    tf32split(Wl[i], hi, lo);
    g_Wh[i] = hi; g_Wlo[i] = lo;
}
__global__ void kSplitG(const float* __restrict__ Wih, const float* __restrict__ Whh) {
    int i = blockIdx.x * 256 + threadIdx.x;
    int j = i >> 10, k = i & 1023;
    float v = (k < 512) ? Wih[j * 512 + k] : Whh[j * 512 + k - 512];
    float hi, lo;
    tf32split(v, hi, lo);
    g_Wgh[i] = hi; g_Wgl[i] = lo;
}
__global__ void kInit(const float* __restrict__ feat) {
    int gid = blockIdx.x * blockDim.x + threadIdx.x;   // 64 x 512
    int b = gid >> 9, u = gid & 511;
    float f = feat[b * 512 + u];
    g_c[b * 512 + u] = 0.f;
    float hi, lo; tf32split(f, hi, lo);
    g_aht[u * 64 + b] = hi; g_alt[u * 64 + b] = lo;
    if (gid < NB) { g_word[gid] = START_TOK; g_mask[gid] = 0; }
    if (gid == 0)   g_done = 0;
}

// ---------------- kGatesM: gates GEMM via mma (tf32-3x), emb gather fused ----
// grid (16, 8): x -> 128 gate rows, y = 128-k slice; 256 thr (8 warps 4m x 2n).
// ky<4: source = emb[word] (gathered + split inline); ky>=4: h from g_aht/g_alt.
__global__ __launch_bounds__(256) void kGatesM(const float* __restrict__ emb) {
    extern __shared__ __align__(16) float sm[];
    if (g_done) return;
    float* ws_hi = sm;
    float* ws_lo = sm + GW_TILE;
    float* hs_hi = sm + 2 * GW_TILE;
    float* hs_lo = sm + 2 * GW_TILE + GH_TILE;
    const int tid = threadIdx.x, lane = tid & 31, wid = tid >> 5;
    const int r0 = blockIdx.x * 128;
    const int ky = blockIdx.y;
    const int kbase = ky * 128;
    const int wm = wid & 3, wn = wid >> 2;
    const int rA = lane >> 2, cA = lane & 3;

    float d[2][4][4];
    #pragma unroll
    for (int mt = 0; mt < 2; mt++)
        #pragma unroll
        for (int nt = 0; nt < 4; nt++)
            #pragma unroll
            for (int j = 0; j < 4; j++) d[mt][nt][j] = 0.f;

    for (int ch = 0; ch < 2; ch++) {
        if (ch) __syncthreads();
        const int kc0 = ch * 64;
        for (int i = tid; i < 4096; i += 256) {     // W: 2 tiles x 128 rows x 16 f4
            int tile = i >> 11, j = i & 2047, row = j >> 4, c4 = j & 15;
            const float* src = (tile ? g_Wgl : g_Wgh)
                             + (size_t)(r0 + row) * 1024 + kbase + kc0 + c4 * 4;
            float* dst = (tile ? ws_lo : ws_hi) + row * 72 + c4 * 4;
            *reinterpret_cast<float4*>(dst) = *reinterpret_cast<const float4*>(src);
        }
        if (ky < 4) {
            // gather emb[word[b]] along k (coalesced), split, store [k][b]
            for (int i = tid; i < 4096; i += 256) {
                int b = i >> 6, k = i & 63;
                float v = emb[(size_t)g_word[b] * 512 + kbase + kc0 + k];
                float hi, lo; tf32split(v, hi, lo);
                hs_hi[k * 72 + b] = hi;
                hs_lo[k * 72 + b] = lo;
            }
        } else {
            const float* hsrc_hi = g_aht + (kbase - 512) * 64;
            const float* hsrc_lo = g_alt + (kbase - 512) * 64;
            for (int i = tid; i < 2048; i += 256) {  // 2 tiles x 64 k x 16 f4
                int tile = i >> 10, j = i & 1023, k = j >> 4, c4 = j & 15;
                const float* src = (tile ? hsrc_lo : hsrc_hi) + (kc0 + k) * 64 + c4 * 4;
                float* dst = (tile ? hs_lo : hs_hi) + k * 72 + c4 * 4;
                *reinterpret_cast<float4*>(dst) = *reinterpret_cast<const float4*>(src);
            }
        }
        __syncthreads();

        #pragma unroll
        for (int k8 = 0; k8 < 8; k8++) {
            const int kb = k8 * 8;
            uint32_t ahi[2][4], alo[2][4], bhi[4][2], blo[4][2];
            #pragma unroll
            for (int mt = 0; mt < 2; mt++) {
                int base = (wm * 32 + mt * 16) * 72;
                #pragma unroll
                for (int j = 0; j < 4; j++) {
                    int off = base + (rA + (j & 1) * 8) * 72 + kb + cA + (j >> 1) * 4;
                    ahi[mt][j] = __float_as_uint(ws_hi[off]);
                    alo[mt][j] = __float_as_uint(ws_lo[off]);
                }
            }
            #pragma unroll
            for (int nt = 0; nt < 4; nt++) {
                int nn = wn * 32 + nt * 8 + rA;
                #pragma unroll
                for (int j = 0; j < 2; j++) {
                    int off = (kb + cA + j * 4) * 72 + nn;
                    bhi[nt][j] = __float_as_uint(hs_hi[off]);
                    blo[nt][j] = __float_as_uint(hs_lo[off]);
                }
            }
            #pragma unroll
            for (int mt = 0; mt < 2; mt++)
                #pragma unroll
                for (int nt = 0; nt < 4; nt++) {
                    mma8(d[mt][nt], ahi[mt], bhi[nt]);
                    mma8(d[mt][nt], ahi[mt], blo[nt]);
                    mma8(d[mt][nt], alo[mt], bhi[nt]);
                }
        }
    }
    __syncthreads();

    float* st = sm;                       // [128][72]
    #pragma unroll
    for (int mt = 0; mt < 2; mt++)
        #pragma unroll
        for (int nt = 0; nt < 4; nt++)
            #pragma unroll
            for (int j = 0; j < 4; j++) {
                int m = wm * 32 + mt * 16 + rA + (j >> 1) * 8;
                int n = wn * 32 + nt * 8 + 2 * cA + (j & 1);
                st[m * 72 + n] = d[mt][nt][j];
            }
    __syncthreads();
    for (int idx = tid; idx < 8192; idx += 256) {
        int b = idx >> 7, rl = idx & 127;
        g_gp[ky][b * 2048 + r0 + rl] = st[rl * 72 + b];
    }
}

// ---------------- kPoint: 8-way partial sum + LSTM + h splits ----------------
__global__ void kPoint(const float* __restrict__ bih, const float* __restrict__ bhh) {
    if (g_done) return;
    int gid = blockIdx.x * blockDim.x + threadIdx.x;
    int b = gid >> 9, u = gid & 511;
    float gate[4];
    #pragma unroll
    for (int q = 0; q < 4; q++) {
        int j = u + 512 * q;
        float s = bih[j] + bhh[j];
        #pragma unroll
        for (int ks = 0; ks < NKS; ks++) s += g_gp[ks][b * 2048 + j];
        gate[q] = s;
    }
    float ii = 1.f / (1.f + expf(-gate[0]));
    float ff = 1.f / (1.f + expf(-gate[1]));
    float gg = tanhf(gate[2]);
    float oo = 1.f / (1.f + expf(-gate[3]));
    float c = ff * g_c[gid] + ii * gg;
    g_c[gid] = c;
    float h = oo * tanhf(c);
    float hi, lo; tf32split(h, hi, lo);
    g_aht[u * 64 + b] = hi; g_alt[u * 64 + b] = lo;
}

// ---------------- kBmma: pipelined tf32-3x logits GEMM, 2 blocks/SM ----------------
// grid 250 x 256 thr (8 warps 4m x 2n): tile M=128 vocab x N=64, 16 chunks K=32.
__global__ __launch_bounds__(256, 2) void kBmma(const float* __restrict__ bl,
                                                float* __restrict__ out, int t) {
    extern __shared__ __align__(16) float sm[];
    const int tid = threadIdx.x, lane = tid & 31, wid = tid >> 5;
    const int blk = blockIdx.x;
    const int r0 = blk * 128;

    if (g_done) {
        for (int idx = tid; idx < 128 * 64; idx += 256) {
            int b = idx >> 7, r = idx & 127;
            out[(size_t)b * (TT * VOC) + (size_t)t * VOC + r0 + r] = 0.f;
        }
        return;
    }

    const uint32_t smb = smem_u32(sm);
    const int wm = wid & 3, wn = wid >> 2;
    const int rA = lane >> 2, cA = lane & 3;

    // stage chunk ch into buffer buf via cp.async (one commit group)
    auto stage = [&](int ch, int buf) {
        const int kc0 = ch * 32;
        uint32_t base = smb + buf * BUF_FLOATS * 4;
        #pragma unroll
        for (int it = 0; it < 8; it++) {            // W: 2048 f4 / 256 thr
            int i = tid + it * 256;
            int tile = i >> 10, j = i & 1023, row = j >> 3, c4 = j & 7;
            const float* src = (tile ? g_Wlo : g_Wh)
                             + (size_t)(r0 + row) * 512 + kc0 + c4 * 4;
            cpa16(base + (tile * WS_TILE + row * 36 + c4 * 4) * 4, src);
        }
        #pragma unroll
        for (int it = 0; it < 4; it++) {            // h: 1024 f4 / 256 thr
            int i = tid + it * 256;
            int tile = i >> 9, j = i & 511, k = j >> 4, c4 = j & 15;
            const float* src = (tile ? g_alt : g_aht) + (kc0 + k) * 64 + c4 * 4;
            cpa16(base + (2 * WS_TILE + tile * HS_TILE + k * 72 + c4 * 4) * 4, src);
        }
        asm volatile("cp.async.commit_group;" ::: "memory");
    };

    float d[2][4][4];
    #pragma unroll
    for (int mt = 0; mt < 2; mt++)
        #pragma unroll
        for (int nt = 0; nt < 4; nt++)
            #pragma unroll
            for (int j = 0; j < 4; j++) d[mt][nt][j] = 0.f;

    stage(0, 0);
    stage(1, 1);

    for (int ch = 0; ch < 16; ch++) {
        if (ch < 15) asm volatile("cp.async.wait_group 1;" ::: "memory");
        else         asm volatile("cp.async.wait_group 0;" ::: "memory");
        __syncthreads();

        const float* base  = sm + (ch & 1) * BUF_FLOATS;
        const float* ws_hi = base;
        const float* ws_lo = base + WS_TILE;
        const float* hs_hi = base + 2 * WS_TILE;
        const float* hs_lo = base + 2 * WS_TILE + HS_TILE;

        #pragma unroll
        for (int k8 = 0; k8 < 4; k8++) {
            const int kb = k8 * 8;
            uint32_t ahi[2][4], alo[2][4], bhi[4][2], blo[4][2];
            #pragma unroll
            for (int mt = 0; mt < 2; mt++) {
                int mbase = (wm * 32 + mt * 16) * 36;
                #pragma unroll
                for (int j = 0; j < 4; j++) {
                    int off = mbase + (rA + (j & 1) * 8) * 36 + kb + cA + (j >> 1) * 4;
                    ahi[mt][j] = __float_as_uint(ws_hi[off]);
                    alo[mt][j] = __float_as_uint(ws_lo[off]);
                }
            }
            #pragma unroll
            for (int nt = 0; nt < 4; nt++) {
                int nn = wn * 32 + nt * 8 + rA;
                #pragma unroll
                for (int j = 0; j < 2; j++) {
                    int off = (kb + cA + j * 4) * 72 + nn;
                    bhi[nt][j] = __float_as_uint(hs_hi[off]);
                    blo[nt][j] = __float_as_uint(hs_lo[off]);
                }
            }
            #pragma unroll
            for (int mt = 0; mt < 2; mt++)
                #pragma unroll
                for (int nt = 0; nt < 4; nt++) {
                    mma8(d[mt][nt], ahi[mt], bhi[nt]);
                    mma8(d[mt][nt], ahi[mt], blo[nt]);
                    mma8(d[mt][nt], alo[mt], bhi[nt]);
                }
        }
        __syncthreads();
        if (ch + 2 < 16) stage(ch + 2, ch & 1);
    }
    __syncthreads();

    // stage D to smem st[128][72]
    float* st = sm;
    #pragma unroll
    for (int mt = 0; mt < 2; mt++)
        #pragma unroll
        for (int nt = 0; nt < 4; nt++)
            #pragma unroll
            for (int j = 0; j < 4; j++) {
                int m = wm * 32 + mt * 16 + rA + (j >> 1) * 8;
                int n = wn * 32 + nt * 8 + 2 * cA + (j & 1);
                st[m * 72 + n] = d[mt][nt][j];
            }
    __syncthreads();

    float* cv = sm + 128 * 72;
    int*   ci = reinterpret_cast<int*>(cv + 256);
    {
        int b = tid >> 2, q = tid & 3;            // thread: batch b, rows q*32..q*32+31
        float best = -1e30f; int bi = 0;
        float* op = out + (size_t)b * (TT * VOC) + (size_t)t * VOC + r0 + q * 32;
        #pragma unroll
        for (int g = 0; g < 8; g++) {
            int rb = q * 32 + g * 4;
            float4 v;
            v.x = st[(rb + 0) * 72 + b] + bl[r0 + rb + 0];
            v.y = st[(rb + 1) * 72 + b] + bl[r0 + rb + 1];
            v.z = st[(rb + 2) * 72 + b] + bl[r0 + rb + 2];
            v.w = st[(rb + 3) * 72 + b] + bl[r0 + rb + 3];
            if (v.x > best) { best = v.x; bi = r0 + rb; }
            if (v.y > best) { best = v.y; bi = r0 + rb + 1; }
            if (v.z > best) { best = v.z; bi = r0 + rb + 2; }
            if (v.w > best) { best = v.w; bi = r0 + rb + 3; }
            stcs4(op + g * 4, v);
        }
        cv[tid] = best; ci[tid] = bi;
    }
    __syncthreads();
    if ((tid & 3) == 0) {
        int b = tid >> 2;
        float best = cv[tid]; int bi = ci[tid];
        #pragma unroll
        for (int q = 1; q < 4; q++) {
            float v = cv[tid + q]; int i = ci[tid + q];
            if (v > best || (v == best && i < bi)) { best = v; bi = i; }
        }
        g_pv[blk * 64 + b] = best; g_pi[blk * 64 + b] = bi;
    }
}

// ---------------- kC: argmax finalize (250 partials) ----------------
__global__ __launch_bounds__(512) void kC() {
    if (g_done) return;
    __shared__ float sv[512];
    __shared__ int   si[512];
    __shared__ int   sm2[64];
    int tid = threadIdx.x;
    int b = tid & 63, q = tid >> 6;               // q 0..7, slices of 32
    int s = q * 32, e = (s + 32 < NPART) ? s + 32 : NPART;
    float best = -1e30f; int bi = 0x7fffffff;
    for (int k = s; k < e; k++) {
        float v = g_pv[k * 64 + b];
        int   i = g_pi[k * 64 + b];
        if (v > best || (v == best && i < bi)) { best = v; bi = i; }
    }
    sv[q * 64 + b] = best; si[q * 64 + b] = bi;
    __syncthreads();
    if (tid < 64) {
        float bvv = sv[tid]; int bix = si[tid];
        #pragma unroll
        for (int q2 = 1; q2 < 8; q2++) {
            float v = sv[q2 * 64 + tid]; int i = si[q2 * 64 + tid];
            if (v > bvv || (v == bvv && i < bix)) { bvv = v; bix = i; }
        }
        g_word[tid] = bix;
        int m = g_mask[tid] | (bix == END_TOK);
        g_mask[tid] = m;
        sm2[tid] = m;
    }
    __syncthreads();
    if (tid == 0) {
        int all = 1;
        for (int b2 = 0; b2 < 64; b2++) all &= sm2[b2];
        if (all) g_done = 1;
    }
}

extern "C" void kernel_launch(void* const* d_in, const int* in_sizes, int n_in,
                              void* d_out, int out_size) {
    const float* feat = (const float*)d_in[0];
    const float* emb  = (const float*)d_in[1];
    const float* Wih  = (const float*)d_in[2];
    const float* Whh  = (const float*)d_in[3];
    const float* bih  = (const float*)d_in[4];
    const float* bhh  = (const float*)d_in[5];
    const float* Wl   = (const float*)d_in[6];
    const float* bl   = (const float*)d_in[7];
    float* out = (float*)d_out;

    cudaFuncSetAttribute(kBmma,  cudaFuncAttributeMaxDynamicSharedMemorySize, BMMA_SMEM);
    cudaFuncSetAttribute(kGatesM, cudaFuncAttributeMaxDynamicSharedMemorySize, GATES_SMEM);

    kSplitW<<<VOC * HID / 256, 256>>>(Wl);
    kSplitG<<<2048 * 1024 / 256, 256>>>(Wih, Whh);
    kInit<<<64, 512>>>(feat);
    for (int t = 0; t < TT; t++) {
        kGatesM<<<dim3(16, 8), 256, GATES_SMEM>>>(emb);
        kPoint<<<64, 512>>>(bih, bhh);
        kBmma<<<NBLK_B, 256, BMMA_SMEM>>>(bl, out, t);
        kC<<<1, 512>>>();
    }
}

// round 16
// speedup vs baseline: 1.2749x; 1.2749x over previous
#include <cuda_runtime.h>
#include <math.h>
#include <stdint.h>

typedef unsigned long long u64;

#define NB    64
#define HID   512
#define VOC   32000
#define TT    50
#define NBLK_B 250
#define NPART 250
#define NKS   8
#define START_TOK 1
#define END_TOK 2

// ---- kBmma smem (floats): 2 buffers of [Whi 128x40 | Wlo 128x40 | hhi 32x72 | hlo 32x72]  (R14)
#define WS_TILE 5120
#define HS_TILE 2304
#define BUF_FLOATS (2 * WS_TILE + 2 * HS_TILE)      // 14848
#define BMMA_SMEM (2 * BUF_FLOATS * 4)              // 118784 bytes
// ---- kGatesM smem (floats): 2 buffers of [Whi 128x36 | Wlo 128x36 | hhi 32x72 | hlo 32x72]
#define GWS_TILE (128 * 36)                         // 4608
#define GHS_TILE (32 * 72)                          // 2304
#define GBUF_FLOATS (2 * GWS_TILE + 2 * GHS_TILE)   // 13824
#define GATES_SMEM (2 * GBUF_FLOATS * 4)            // 110592 bytes

// ---------------- device scratch ----------------
__device__ float g_Wh[VOC * HID];          // W_lin tf32-hi [r][k]
__device__ float g_Wlo[VOC * HID];         // W_lin tf32-lo [r][k]
__device__ float g_Wgh[2048 * 1024];       // gates W combined hi [j][k]
__device__ float g_Wgl[2048 * 1024];       // gates W combined lo
__device__ float g_aht[HID * NB];          // h tf32-hi transposed [k][b]
__device__ float g_alt[HID * NB];          // h tf32-lo transposed [k][b]
__device__ float g_xht[HID * NB];          // x=emb[word] tf32-hi transposed [k][b]
__device__ float g_xlt[HID * NB];          // x tf32-lo
__device__ float g_c[NB * HID];
__device__ float g_gp[NKS][NB * 2048];     // split-K gate partials
__device__ int   g_word[NB];
__device__ int   g_mask[NB];
__device__ int   g_done;
__device__ float g_pv[NPART * NB];
__device__ int   g_pi[NPART * NB];

// ---------------- helpers ----------------
__device__ __forceinline__ void stcs4(float* p, float4 v) {
    asm volatile("st.global.cs.v4.f32 [%0], {%1, %2, %3, %4};"
                 :: "l"(p), "f"(v.x), "f"(v.y), "f"(v.z), "f"(v.w) : "memory");
}
__device__ __forceinline__ void tf32split(float f, float &hi, float &lo) {
    uint32_t hb, lb;
    asm("cvt.rna.tf32.f32 %0, %1;" : "=r"(hb) : "f"(f));
    hi = __uint_as_float(hb);
    float r = f - hi;
    asm("cvt.rna.tf32.f32 %0, %1;" : "=r"(lb) : "f"(r));
    lo = __uint_as_float(lb);
}
__device__ __forceinline__ void mma8(float (&d)[4], const uint32_t (&a)[4],
                                     const uint32_t (&b)[2]) {
    asm("mma.sync.aligned.m16n8k8.row.col.f32.tf32.tf32.f32 "
        "{%0,%1,%2,%3}, {%4,%5,%6,%7}, {%8,%9}, {%0,%1,%2,%3};"
        : "+f"(d[0]), "+f"(d[1]), "+f"(d[2]), "+f"(d[3])
        : "r"(a[0]), "r"(a[1]), "r"(a[2]), "r"(a[3]), "r"(b[0]), "r"(b[1]));
}
__device__ __forceinline__ uint32_t smem_u32(const void* p) {
    uint32_t a;
    asm("{ .reg .u64 t; cvta.to.shared.u64 t, %1; cvt.u32.u64 %0, t; }" : "=r"(a) : "l"(p));
    return a;
}
__device__ __forceinline__ void cpa16(uint32_t saddr, const float* g) {
    asm volatile("cp.async.ca.shared.global [%0], [%1], 16;" :: "r"(saddr), "l"(g));
}

// ---------------- once-per-replay transforms ----------------
__global__ void kSplitW(const float* __restrict__ Wl) {
    int i = blockIdx.x * 256 + threadIdx.x;
    float hi, lo;
    tf32split(Wl[i], hi, lo);
    g_Wh[i] = hi; g_Wlo[i] = lo;
}
__global__ void kSplitG(const float* __restrict__ Wih, const float* __restrict__ Whh) {
    int i = blockIdx.x * 256 + threadIdx.x;
    int j = i >> 10, k = i & 1023;
    float v = (k < 512) ? Wih[j * 512 + k] : Whh[j * 512 + k - 512];
    float hi, lo;
    tf32split(v, hi, lo);
    g_Wgh[i] = hi; g_Wgl[i] = lo;
}
__global__ void kInit(const float* __restrict__ feat) {
    int gid = blockIdx.x * blockDim.x + threadIdx.x;   // 64 x 512
    int b = gid >> 9, u = gid & 511;
    float f = feat[b * 512 + u];
    g_c[b * 512 + u] = 0.f;
    float hi, lo; tf32split(f, hi, lo);
    g_aht[u * 64 + b] = hi; g_alt[u * 64 + b] = lo;
    if (gid < NB) { g_word[gid] = START_TOK; g_mask[gid] = 0; }
    if (gid == 0)   g_done = 0;
}

// ---------------- kEmb: gather emb[word] + tf32 split, transposed ----------------
__global__ void kEmb(const float* __restrict__ emb) {
    if (g_done) return;
    int b = blockIdx.x, u = threadIdx.x;      // 64 blocks x 512
    float v = emb[(size_t)g_word[b] * 512 + u];
    float hi, lo; tf32split(v, hi, lo);
    g_xht[u * 64 + b] = hi; g_xlt[u * 64 + b] = lo;
}

// ---------------- kGatesM: pipelined gates GEMM via mma (tf32-3x) ----------------
// grid (16, 8): x -> 128 gate rows, y = 128-k slice; 256 thr (8 warps 4m x 2n).
// 4 K-chunks of 32, cp.async double-buffered (kBmma-style).
__global__ __launch_bounds__(256) void kGatesM() {
    extern __shared__ __align__(16) float sm[];
    if (g_done) return;
    const int tid = threadIdx.x, lane = tid & 31, wid = tid >> 5;
    const int r0 = blockIdx.x * 128;
    const int ky = blockIdx.y;
    const int kbase = ky * 128;
    const int wm = wid & 3, wn = wid >> 2;
    const int rA = lane >> 2, cA = lane & 3;

    const uint32_t smb = smem_u32(sm);
    const float* hsrc_hi = (ky < 4) ? (g_xht + kbase * 64) : (g_aht + (kbase - 512) * 64);
    const float* hsrc_lo = (ky < 4) ? (g_xlt + kbase * 64) : (g_alt + (kbase - 512) * 64);

    auto stage = [&](int ch, int buf) {
        const int kc0 = ch * 32;
        uint32_t base = smb + buf * GBUF_FLOATS * 4;
        #pragma unroll
        for (int it = 0; it < 8; it++) {            // W: 2048 f4 / 256 thr
            int i = tid + it * 256;
            int tile = i >> 10, j = i & 1023, row = j >> 3, c4 = j & 7;
            const float* src = (tile ? g_Wgl : g_Wgh)
                             + (size_t)(r0 + row) * 1024 + kbase + kc0 + c4 * 4;
            cpa16(base + (tile * GWS_TILE + row * 36 + c4 * 4) * 4, src);
        }
        #pragma unroll
        for (int it = 0; it < 4; it++) {            // h: 1024 f4 / 256 thr
            int i = tid + it * 256;
            int tile = i >> 9, j = i & 511, k = j >> 4, c4 = j & 15;
            const float* src = (tile ? hsrc_lo : hsrc_hi) + (kc0 + k) * 64 + c4 * 4;
            cpa16(base + (2 * GWS_TILE + tile * GHS_TILE + k * 72 + c4 * 4) * 4, src);
        }
        asm volatile("cp.async.commit_group;" ::: "memory");
    };

    float d[2][4][4];
    #pragma unroll
    for (int mt = 0; mt < 2; mt++)
        #pragma unroll
        for (int nt = 0; nt < 4; nt++)
            #pragma unroll
            for (int j = 0; j < 4; j++) d[mt][nt][j] = 0.f;

    stage(0, 0);
    stage(1, 1);

    for (int ch = 0; ch < 4; ch++) {
        if (ch < 3) asm volatile("cp.async.wait_group 1;" ::: "memory");
        else        asm volatile("cp.async.wait_group 0;" ::: "memory");
        __syncthreads();

        const float* base  = sm + (ch & 1) * GBUF_FLOATS;
        const float* ws_hi = base;
        const float* ws_lo = base + GWS_TILE;
        const float* hs_hi = base + 2 * GWS_TILE;
        const float* hs_lo = base + 2 * GWS_TILE + GHS_TILE;

        #pragma unroll
        for (int k8 = 0; k8 < 4; k8++) {
            const int kb = k8 * 8;
            uint32_t ahi[2][4], alo[2][4], bhi[4][2], blo[4][2];
            #pragma unroll
            for (int mt = 0; mt < 2; mt++) {
                int mbase = (wm * 32 + mt * 16) * 36;
                #pragma unroll
                for (int j = 0; j < 4; j++) {
                    int off = mbase + (rA + (j & 1) * 8) * 36 + kb + cA + (j >> 1) * 4;
                    ahi[mt][j] = __float_as_uint(ws_hi[off]);
                    alo[mt][j] = __float_as_uint(ws_lo[off]);
                }
            }
            #pragma unroll
            for (int nt = 0; nt < 4; nt++) {
                int nn = wn * 32 + nt * 8 + rA;
                #pragma unroll
                for (int j = 0; j < 2; j++) {
                    int off = (kb + cA + j * 4) * 72 + nn;
                    bhi[nt][j] = __float_as_uint(hs_hi[off]);
                    blo[nt][j] = __float_as_uint(hs_lo[off]);
                }
            }
            #pragma unroll
            for (int mt = 0; mt < 2; mt++)
                #pragma unroll
                for (int nt = 0; nt < 4; nt++) {
                    mma8(d[mt][nt], ahi[mt], bhi[nt]);
                    mma8(d[mt][nt], ahi[mt], blo[nt]);
                    mma8(d[mt][nt], alo[mt], bhi[nt]);
                }
        }
        __syncthreads();
        if (ch + 2 < 4) stage(ch + 2, ch & 1);
    }
    __syncthreads();

    float* st = sm;                       // [128][72]
    #pragma unroll
    for (int mt = 0; mt < 2; mt++)
        #pragma unroll
        for (int nt = 0; nt < 4; nt++)
            #pragma unroll
            for (int j = 0; j < 4; j++) {
                int m = wm * 32 + mt * 16 + rA + (j >> 1) * 8;
                int n = wn * 32 + nt * 8 + 2 * cA + (j & 1);
                st[m * 72 + n] = d[mt][nt][j];
            }
    __syncthreads();
    for (int idx = tid; idx < 8192; idx += 256) {
        int b = idx >> 7, rl = idx & 127;
        g_gp[ky][b * 2048 + r0 + rl] = st[rl * 72 + b];
    }
}

// ---------------- kPoint: 8-way partial sum + LSTM + h splits ----------------
__global__ void kPoint(const float* __restrict__ bih, const float* __restrict__ bhh) {
    if (g_done) return;
    int gid = blockIdx.x * blockDim.x + threadIdx.x;
    int b = gid >> 9, u = gid & 511;
    float gate[4];
    #pragma unroll
    for (int q = 0; q < 4; q++) {
        int j = u + 512 * q;
        float s = bih[j] + bhh[j];
        #pragma unroll
        for (int ks = 0; ks < NKS; ks++) s += g_gp[ks][b * 2048 + j];
        gate[q] = s;
    }
    float ii = 1.f / (1.f + expf(-gate[0]));
    float ff = 1.f / (1.f + expf(-gate[1]));
    float gg = tanhf(gate[2]);
    float oo = 1.f / (1.f + expf(-gate[3]));
    float c = ff * g_c[gid] + ii * gg;
    g_c[gid] = c;
    float h = oo * tanhf(c);
    float hi, lo; tf32split(h, hi, lo);
    g_aht[u * 64 + b] = hi; g_alt[u * 64 + b] = lo;
}

// ---------------- kBmma: pipelined tf32-3x logits GEMM (R14, unchanged) ----------------
// grid 250 x 256 thr (8 warps 4m x 2n): tile M=128 vocab x N=64, 16 chunks K=32.
__global__ __launch_bounds__(256) void kBmma(const float* __restrict__ bl,
                                             float* __restrict__ out, int t) {
    extern __shared__ __align__(16) float sm[];
    const int tid = threadIdx.x, lane = tid & 31, wid = tid >> 5;
    const int blk = blockIdx.x;
    const int r0 = blk * 128;

    if (g_done) {
        for (int idx = tid; idx < 128 * 64; idx += 256) {
            int b = idx >> 7, r = idx & 127;
            out[(size_t)b * (TT * VOC) + (size_t)t * VOC + r0 + r] = 0.f;
        }
        return;
    }

    const uint32_t smb = smem_u32(sm);
    const int wm = wid & 3, wn = wid >> 2;
    const int rA = lane >> 2, cA = lane & 3;

    auto stage = [&](int ch, int buf) {
        const int kc0 = ch * 32;
        uint32_t base = smb + buf * BUF_FLOATS * 4;
        #pragma unroll
        for (int it = 0; it < 8; it++) {            // W: 2048 f4 / 256 thr
            int i = tid + it * 256;
            int tile = i >> 10, j = i & 1023, row = j >> 3, c4 = j & 7;
            const float* src = (tile ? g_Wlo : g_Wh)
                             + (size_t)(r0 + row) * 512 + kc0 + c4 * 4;
            cpa16(base + (tile * WS_TILE + row * 40 + c4 * 4) * 4, src);
        }
        #pragma unroll
        for (int it = 0; it < 4; it++) {            // h: 1024 f4 / 256 thr
            int i = tid + it * 256;
            int tile = i >> 9, j = i & 511, k = j >> 4, c4 = j & 15;
            const float* src = (tile ? g_alt : g_aht) + (kc0 + k) * 64 + c4 * 4;
            cpa16(base + (2 * WS_TILE + tile * HS_TILE + k * 72 + c4 * 4) * 4, src);
        }
        asm volatile("cp.async.commit_group;" ::: "memory");
    };

    float d[2][4][4];
    #pragma unroll
    for (int mt = 0; mt < 2; mt++)
        #pragma unroll
        for (int nt = 0; nt < 4; nt++)
            #pragma unroll
            for (int j = 0; j < 4; j++) d[mt][nt][j] = 0.f;

    stage(0, 0);
    stage(1, 1);

    for (int ch = 0; ch < 16; ch++) {
        if (ch < 15) asm volatile("cp.async.wait_group 1;" ::: "memory");
        else         asm volatile("cp.async.wait_group 0;" ::: "memory");
        __syncthreads();

        const float* base  = sm + (ch & 1) * BUF_FLOATS;
        const float* ws_hi = base;
        const float* ws_lo = base + WS_TILE;
        const float* hs_hi = base + 2 * WS_TILE;
        const float* hs_lo = base + 2 * WS_TILE + HS_TILE;

        #pragma unroll
        for (int k8 = 0; k8 < 4; k8++) {
            const int kb = k8 * 8;
            uint32_t ahi[2][4], alo[2][4], bhi[4][2], blo[4][2];
            #pragma unroll
            for (int mt = 0; mt < 2; mt++) {
                int mbase = (wm * 32 + mt * 16) * 40;
                #pragma unroll
                for (int j = 0; j < 4; j++) {
                    int off = mbase + (rA + (j & 1) * 8) * 40 + kb + cA + (j >> 1) * 4;
                    ahi[mt][j] = __float_as_uint(ws_hi[off]);
                    alo[mt][j] = __float_as_uint(ws_lo[off]);
                }
            }
            #pragma unroll
            for (int nt = 0; nt < 4; nt++) {
                int nn = wn * 32 + nt * 8 + rA;
                #pragma unroll
                for (int j = 0; j < 2; j++) {
                    int off = (kb + cA + j * 4) * 72 + nn;
                    bhi[nt][j] = __float_as_uint(hs_hi[off]);
                    blo[nt][j] = __float_as_uint(hs_lo[off]);
                }
            }
            #pragma unroll
            for (int mt = 0; mt < 2; mt++)
                #pragma unroll
                for (int nt = 0; nt < 4; nt++) {
                    mma8(d[mt][nt], ahi[mt], bhi[nt]);
                    mma8(d[mt][nt], ahi[mt], blo[nt]);
                    mma8(d[mt][nt], alo[mt], bhi[nt]);
                }
        }
        __syncthreads();
        if (ch + 2 < 16) stage(ch + 2, ch & 1);
    }
    __syncthreads();

    // stage D to smem st[128][72]
    float* st = sm;
    #pragma unroll
    for (int mt = 0; mt < 2; mt++)
        #pragma unroll
        for (int nt = 0; nt < 4; nt++)
            #pragma unroll
            for (int j = 0; j < 4; j++) {
                int m = wm * 32 + mt * 16 + rA + (j >> 1) * 8;
                int n = wn * 32 + nt * 8 + 2 * cA + (j & 1);
                st[m * 72 + n] = d[mt][nt][j];
            }
    __syncthreads();

    float* cv = sm + 128 * 72;
    int*   ci = reinterpret_cast<int*>(cv + 256);
    {
        int b = tid >> 2, q = tid & 3;
        float best = -1e30f; int bi = 0;
        float* op = out + (size_t)b * (TT * VOC) + (size_t)t * VOC + r0 + q * 32;
        #pragma unroll
        for (int g = 0; g < 8; g++) {
            int rb = q * 32 + g * 4;
            float4 v;
            v.x = st[(rb + 0) * 72 + b] + bl[r0 + rb + 0];
            v.y = st[(rb + 1) * 72 + b] + bl[r0 + rb + 1];
            v.z = st[(rb + 2) * 72 + b] + bl[r0 + rb + 2];
            v.w = st[(rb + 3) * 72 + b] + bl[r0 + rb + 3];
            if (v.x > best) { best = v.x; bi = r0 + rb; }
            if (v.y > best) { best = v.y; bi = r0 + rb + 1; }
            if (v.z > best) { best = v.z; bi = r0 + rb + 2; }
            if (v.w > best) { best = v.w; bi = r0 + rb + 3; }
            stcs4(op + g * 4, v);
        }
        cv[tid] = best; ci[tid] = bi;
    }
    __syncthreads();
    if ((tid & 3) == 0) {
        int b = tid >> 2;
        float best = cv[tid]; int bi = ci[tid];
        #pragma unroll
        for (int q = 1; q < 4; q++) {
            float v = cv[tid + q]; int i = ci[tid + q];
            if (v > best || (v == best && i < bi)) { best = v; bi = i; }
        }
        g_pv[blk * 64 + b] = best; g_pi[blk * 64 + b] = bi;
    }
}

// ---------------- kC: argmax finalize (250 partials) ----------------
__global__ __launch_bounds__(512) void kC() {
    if (g_done) return;
    __shared__ float sv[512];
    __shared__ int   si[512];
    __shared__ int   sm2[64];
    int tid = threadIdx.x;
    int b = tid & 63, q = tid >> 6;
    int s = q * 32, e = (s + 32 < NPART) ? s + 32 : NPART;
    float best = -1e30f; int bi = 0x7fffffff;
    for (int k = s; k < e; k++) {
        float v = g_pv[k * 64 + b];
        int   i = g_pi[k * 64 + b];
        if (v > best || (v == best && i < bi)) { best = v; bi = i; }
    }
    sv[q * 64 + b] = best; si[q * 64 + b] = bi;
    __syncthreads();
    if (tid < 64) {
        float bvv = sv[tid]; int bix = si[tid];
        #pragma unroll
        for (int q2 = 1; q2 < 8; q2++) {
            float v = sv[q2 * 64 + tid]; int i = si[q2 * 64 + tid];
            if (v > bvv || (v == bvv && i < bix)) { bvv = v; bix = i; }
        }
        g_word[tid] = bix;
        int m = g_mask[tid] | (bix == END_TOK);
        g_mask[tid] = m;
        sm2[tid] = m;
    }
    __syncthreads();
    if (tid == 0) {
        int all = 1;
        for (int b2 = 0; b2 < 64; b2++) all &= sm2[b2];
        if (all) g_done = 1;
    }
}

extern "C" void kernel_launch(void* const* d_in, const int* in_sizes, int n_in,
                              void* d_out, int out_size) {
    const float* feat = (const float*)d_in[0];
    const float* emb  = (const float*)d_in[1];
    const float* Wih  = (const float*)d_in[2];
    const float* Whh  = (const float*)d_in[3];
    const float* bih  = (const float*)d_in[4];
    const float* bhh  = (const float*)d_in[5];
    const float* Wl   = (const float*)d_in[6];
    const float* bl   = (const float*)d_in[7];
    float* out = (float*)d_out;

    cudaFuncSetAttribute(kBmma,   cudaFuncAttributeMaxDynamicSharedMemorySize, BMMA_SMEM);
    cudaFuncSetAttribute(kGatesM, cudaFuncAttributeMaxDynamicSharedMemorySize, GATES_SMEM);

    kSplitW<<<VOC * HID / 256, 256>>>(Wl);
    kSplitG<<<2048 * 1024 / 256, 256>>>(Wih, Whh);
    kInit<<<64, 512>>>(feat);
    for (int t = 0; t < TT; t++) {
        kEmb<<<64, 512>>>(emb);
        kGatesM<<<dim3(16, 8), 256, GATES_SMEM>>>();
        kPoint<<<64, 512>>>(bih, bhh);
        kBmma<<<NBLK_B, 256, BMMA_SMEM>>>(bl, out, t);
        kC<<<1, 512>>>();
    }
}

// round 17
// speedup vs baseline: 1.3113x; 1.0286x over previous
#include <cuda_runtime.h>
#include <math.h>
#include <stdint.h>

typedef unsigned long long u64;

#define NB    64
#define HID   512
#define VOC   32000
#define TT    50
#define NBLK_B 250
#define NPART 250
#define NKS   8
#define START_TOK 1
#define END_TOK 2

// ---- kBmma smem (floats): 2 buffers of [Whi 128x40 | Wlo 128x40 | hhi 64x36 | hlo 64x36]
#define WS_TILE 5120
#define HS_TILE 2304
#define BUF_FLOATS (2 * WS_TILE + 2 * HS_TILE)      // 14848
#define BMMA_SMEM (2 * BUF_FLOATS * 4)              // 118784 bytes
// ---- kGatesM smem (floats): 2 buffers of [Whi 128x36 | Wlo 128x36 | hhi 64x36 | hlo 64x36]
#define GWS_TILE (128 * 36)                         // 4608
#define GHS_TILE (64 * 36)                          // 2304
#define GBUF_FLOATS (2 * GWS_TILE + 2 * GHS_TILE)   // 13824
#define GATES_SMEM (2 * GBUF_FLOATS * 4)            // 110592 bytes

// ---------------- device scratch ----------------
__device__ float g_Wh[VOC * HID];          // W_lin tf32-hi [r][k]
__device__ float g_Wlo[VOC * HID];         // W_lin tf32-lo [r][k]
__device__ float g_Eh[VOC * HID];          // embedding tf32-hi [v][k]
__device__ float g_El[VOC * HID];          // embedding tf32-lo [v][k]
__device__ float g_Wgh[2048 * 1024];       // gates W combined hi [j][k]
__device__ float g_Wgl[2048 * 1024];       // gates W combined lo
__device__ float g_ah[NB * HID];           // h tf32-hi [b][k]
__device__ float g_al[NB * HID];           // h tf32-lo [b][k]
__device__ float g_c[NB * HID];
__device__ float g_gp[NKS][NB * 2048];     // split-K gate partials
__device__ int   g_word[NB];
__device__ int   g_mask[NB];
__device__ int   g_done;
__device__ float g_pv[NPART * NB];
__device__ int   g_pi[NPART * NB];

// ---------------- helpers ----------------
__device__ __forceinline__ void stcs4(float* p, float4 v) {
    asm volatile("st.global.cs.v4.f32 [%0], {%1, %2, %3, %4};"
                 :: "l"(p), "f"(v.x), "f"(v.y), "f"(v.z), "f"(v.w) : "memory");
}
__device__ __forceinline__ void tf32split(float f, float &hi, float &lo) {
    uint32_t hb, lb;
    asm("cvt.rna.tf32.f32 %0, %1;" : "=r"(hb) : "f"(f));
    hi = __uint_as_float(hb);
    float r = f - hi;
    asm("cvt.rna.tf32.f32 %0, %1;" : "=r"(lb) : "f"(r));
    lo = __uint_as_float(lb);
}
__device__ __forceinline__ void mma8(float (&d)[4], const uint32_t (&a)[4],
                                     const uint32_t (&b)[2]) {
    asm("mma.sync.aligned.m16n8k8.row.col.f32.tf32.tf32.f32 "
        "{%0,%1,%2,%3}, {%4,%5,%6,%7}, {%8,%9}, {%0,%1,%2,%3};"
        : "+f"(d[0]), "+f"(d[1]), "+f"(d[2]), "+f"(d[3])
        : "r"(a[0]), "r"(a[1]), "r"(a[2]), "r"(a[3]), "r"(b[0]), "r"(b[1]));
}
__device__ __forceinline__ uint32_t smem_u32(const void* p) {
    uint32_t a;
    asm("{ .reg .u64 t; cvta.to.shared.u64 t, %1; cvt.u32.u64 %0, t; }" : "=r"(a) : "l"(p));
    return a;
}
__device__ __forceinline__ void cpa16(uint32_t saddr, const float* g) {
    asm volatile("cp.async.ca.shared.global [%0], [%1], 16;" :: "r"(saddr), "l"(g));
}

// ---------------- once-per-replay transforms ----------------
__global__ void kSplitW(const float* __restrict__ Wl) {
    int i = blockIdx.x * 256 + threadIdx.x;
    float hi, lo;
    tf32split(Wl[i], hi, lo);
    g_Wh[i] = hi; g_Wlo[i] = lo;
}
__global__ void kSplitE(const float* __restrict__ emb) {
    int i = blockIdx.x * 256 + threadIdx.x;
    float hi, lo;
    tf32split(emb[i], hi, lo);
    g_Eh[i] = hi; g_El[i] = lo;
}
__global__ void kSplitG(const float* __restrict__ Wih, const float* __restrict__ Whh) {
    int i = blockIdx.x * 256 + threadIdx.x;
    int j = i >> 10, k = i & 1023;
    float v = (k < 512) ? Wih[j * 512 + k] : Whh[j * 512 + k - 512];
    float hi, lo;
    tf32split(v, hi, lo);
    g_Wgh[i] = hi; g_Wgl[i] = lo;
}
__global__ void kInit(const float* __restrict__ feat) {
    int gid = blockIdx.x * blockDim.x + threadIdx.x;   // 64 x 512
    float f = feat[gid];
    g_c[gid] = 0.f;
    float hi, lo; tf32split(f, hi, lo);
    g_ah[gid] = hi; g_al[gid] = lo;
    if (gid < NB) { g_word[gid] = START_TOK; g_mask[gid] = 0; }
    if (gid == 0)   g_done = 0;
}

// ---------------- kGatesM: pipelined gates GEMM via mma (tf32-3x) ----------------
// grid (16, 8): x -> 128 gate rows, y = 128-k slice; 256 thr (8 warps 4m x 2n).
// ky<4: source = g_Eh/g_El[word[b]] (gathered in cp.async stage); ky>=4: h.
__global__ __launch_bounds__(256) void kGatesM() {
    extern __shared__ __align__(16) float sm[];
    if (g_done) return;
    const int tid = threadIdx.x, lane = tid & 31, wid = tid >> 5;
    const int r0 = blockIdx.x * 128;
    const int ky = blockIdx.y;
    const int kbase = ky * 128;
    const int wm = wid & 3, wn = wid >> 2;
    const int rA = lane >> 2, cA = lane & 3;

    const uint32_t smb = smem_u32(sm);
    const bool useEmb = (ky < 4);
    const int hoff = useEmb ? kbase : (kbase - 512);

    auto stage = [&](int ch, int buf) {
        const int kc0 = ch * 32;
        uint32_t base = smb + buf * GBUF_FLOATS * 4;
        #pragma unroll
        for (int it = 0; it < 8; it++) {            // W: 2048 f4 / 256 thr
            int i = tid + it * 256;
            int tile = i >> 10, j = i & 1023, row = j >> 3, c4 = j & 7;
            const float* src = (tile ? g_Wgl : g_Wgh)
                             + (size_t)(r0 + row) * 1024 + kbase + kc0 + c4 * 4;
            cpa16(base + (tile * GWS_TILE + row * 36 + c4 * 4) * 4, src);
        }
        #pragma unroll
        for (int it = 0; it < 4; it++) {            // h/x: 1024 f4 / 256 thr, [b][k]
            int i = tid + it * 256;
            int tile = i >> 9, j = i & 511, b = j >> 3, f = j & 7;
            const float* src;
            if (useEmb)
                src = (tile ? g_El : g_Eh)
                    + (size_t)g_word[b] * 512 + hoff + kc0 + f * 4;
            else
                src = (tile ? g_al : g_ah) + b * 512 + hoff + kc0 + f * 4;
            cpa16(base + (2 * GWS_TILE + tile * GHS_TILE + b * 36 + f * 4) * 4, src);
        }
        asm volatile("cp.async.commit_group;" ::: "memory");
    };

    float d[2][4][4];
    #pragma unroll
    for (int mt = 0; mt < 2; mt++)
        #pragma unroll
        for (int nt = 0; nt < 4; nt++)
            #pragma unroll
            for (int j = 0; j < 4; j++) d[mt][nt][j] = 0.f;

    stage(0, 0);
    stage(1, 1);

    for (int ch = 0; ch < 4; ch++) {
        if (ch < 3) asm volatile("cp.async.wait_group 1;" ::: "memory");
        else        asm volatile("cp.async.wait_group 0;" ::: "memory");
        __syncthreads();

        const float* base  = sm + (ch & 1) * GBUF_FLOATS;
        const float* ws_hi = base;
        const float* ws_lo = base + GWS_TILE;
        const float* hs_hi = base + 2 * GWS_TILE;
        const float* hs_lo = base + 2 * GWS_TILE + GHS_TILE;

        #pragma unroll
        for (int k8 = 0; k8 < 4; k8++) {
            const int kb = k8 * 8;
            uint32_t ahi[2][4], alo[2][4], bhi[4][2], blo[4][2];
            #pragma unroll
            for (int mt = 0; mt < 2; mt++) {
                int mbase = (wm * 32 + mt * 16) * 36;
                #pragma unroll
                for (int j = 0; j < 4; j++) {
                    int off = mbase + (rA + (j & 1) * 8) * 36 + kb + cA + (j >> 1) * 4;
                    ahi[mt][j] = __float_as_uint(ws_hi[off]);
                    alo[mt][j] = __float_as_uint(ws_lo[off]);
                }
            }
            #pragma unroll
            for (int nt = 0; nt < 4; nt++) {
                int nn = wn * 32 + nt * 8 + rA;
                #pragma unroll
                for (int j = 0; j < 2; j++) {
                    int off = nn * 36 + kb + cA + j * 4;
                    bhi[nt][j] = __float_as_uint(hs_hi[off]);
                    blo[nt][j] = __float_as_uint(hs_lo[off]);
                }
            }
            #pragma unroll
            for (int mt = 0; mt < 2; mt++)
                #pragma unroll
                for (int nt = 0; nt < 4; nt++) {
                    mma8(d[mt][nt], ahi[mt], bhi[nt]);
                    mma8(d[mt][nt], ahi[mt], blo[nt]);
                    mma8(d[mt][nt], alo[mt], bhi[nt]);
                }
        }
        __syncthreads();
        if (ch + 2 < 4) stage(ch + 2, ch & 1);
    }
    __syncthreads();

    float* st = sm;                       // [128][72]
    #pragma unroll
    for (int mt = 0; mt < 2; mt++)
        #pragma unroll
        for (int nt = 0; nt < 4; nt++)
            #pragma unroll
            for (int j = 0; j < 4; j++) {
                int m = wm * 32 + mt * 16 + rA + (j >> 1) * 8;
                int n = wn * 32 + nt * 8 + 2 * cA + (j & 1);
                st[m * 72 + n] = d[mt][nt][j];
            }
    __syncthreads();
    for (int idx = tid; idx < 8192; idx += 256) {
        int b = idx >> 7, rl = idx & 127;
        g_gp[ky][b * 2048 + r0 + rl] = st[rl * 72 + b];
    }
}

// ---------------- kPoint: 8-way partial sum + LSTM + h splits [b][k] ----------------
__global__ void kPoint(const float* __restrict__ bih, const float* __restrict__ bhh) {
    if (g_done) return;
    int gid = blockIdx.x * blockDim.x + threadIdx.x;
    int b = gid >> 9, u = gid & 511;
    float gate[4];
    #pragma unroll
    for (int q = 0; q < 4; q++) {
        int j = u + 512 * q;
        float s = bih[j] + bhh[j];
        #pragma unroll
        for (int ks = 0; ks < NKS; ks++) s += g_gp[ks][b * 2048 + j];
        gate[q] = s;
    }
    float ii = 1.f / (1.f + expf(-gate[0]));
    float ff = 1.f / (1.f + expf(-gate[1]));
    float gg = tanhf(gate[2]);
    float oo = 1.f / (1.f + expf(-gate[3]));
    float c = ff * g_c[gid] + ii * gg;
    g_c[gid] = c;
    float h = oo * tanhf(c);
    float hi, lo; tf32split(h, hi, lo);
    g_ah[gid] = hi; g_al[gid] = lo;
}

// ---------------- kBmma: pipelined tf32-3x logits GEMM ----------------
// grid 250 x 256 thr (8 warps 4m x 2n): tile M=128 vocab x N=64, 16 chunks K=32.
__global__ __launch_bounds__(256) void kBmma(const float* __restrict__ bl,
                                             float* __restrict__ out, int t) {
    extern __shared__ __align__(16) float sm[];
    const int tid = threadIdx.x, lane = tid & 31, wid = tid >> 5;
    const int blk = blockIdx.x;
    const int r0 = blk * 128;

    if (g_done) {
        for (int idx = tid; idx < 128 * 64; idx += 256) {
            int b = idx >> 7, r = idx & 127;
            out[(size_t)b * (TT * VOC) + (size_t)t * VOC + r0 + r] = 0.f;
        }
        return;
    }

    const uint32_t smb = smem_u32(sm);
    const int wm = wid & 3, wn = wid >> 2;
    const int rA = lane >> 2, cA = lane & 3;

    auto stage = [&](int ch, int buf) {
        const int kc0 = ch * 32;
        uint32_t base = smb + buf * BUF_FLOATS * 4;
        #pragma unroll
        for (int it = 0; it < 8; it++) {            // W: 2048 f4 / 256 thr
            int i = tid + it * 256;
            int tile = i >> 10, j = i & 1023, row = j >> 3, c4 = j & 7;
            const float* src = (tile ? g_Wlo : g_Wh)
                             + (size_t)(r0 + row) * 512 + kc0 + c4 * 4;
            cpa16(base + (tile * WS_TILE + row * 40 + c4 * 4) * 4, src);
        }
        #pragma unroll
        for (int it = 0; it < 4; it++) {            // h: 1024 f4 / 256 thr, [b][k]
            int i = tid + it * 256;
            int tile = i >> 9, j = i & 511, b = j >> 3, f = j & 7;
            const float* src = (tile ? g_al : g_ah) + b * 512 + kc0 + f * 4;
            cpa16(base + (2 * WS_TILE + tile * HS_TILE + b * 36 + f * 4) * 4, src);
        }
        asm volatile("cp.async.commit_group;" ::: "memory");
    };

    float d[2][4][4];
    #pragma unroll
    for (int mt = 0; mt < 2; mt++)
        #pragma unroll
        for (int nt = 0; nt < 4; nt++)
            #pragma unroll
            for (int j = 0; j < 4; j++) d[mt][nt][j] = 0.f;

    stage(0, 0);
    stage(1, 1);

    for (int ch = 0; ch < 16; ch++) {
        if (ch < 15) asm volatile("cp.async.wait_group 1;" ::: "memory");
        else         asm volatile("cp.async.wait_group 0;" ::: "memory");
        __syncthreads();

        const float* base  = sm + (ch & 1) * BUF_FLOATS;
        const float* ws_hi = base;
        const float* ws_lo = base + WS_TILE;
        const float* hs_hi = base + 2 * WS_TILE;
        const float* hs_lo = base + 2 * WS_TILE + HS_TILE;

        #pragma unroll
        for (int k8 = 0; k8 < 4; k8++) {
            const int kb = k8 * 8;
            uint32_t ahi[2][4], alo[2][4], bhi[4][2], blo[4][2];
            #pragma unroll
            for (int mt = 0; mt < 2; mt++) {
                int mbase = (wm * 32 + mt * 16) * 40;
                #pragma unroll
                for (int j = 0; j < 4; j++) {
                    int off = mbase + (rA + (j & 1) * 8) * 40 + kb + cA + (j >> 1) * 4;
                    ahi[mt][j] = __float_as_uint(ws_hi[off]);
                    alo[mt][j] = __float_as_uint(ws_lo[off]);
                }
            }
            #pragma unroll
            for (int nt = 0; nt < 4; nt++) {
                int nn = wn * 32 + nt * 8 + rA;
                #pragma unroll
                for (int j = 0; j < 2; j++) {
                    int off = nn * 36 + kb + cA + j * 4;
                    bhi[nt][j] = __float_as_uint(hs_hi[off]);
                    blo[nt][j] = __float_as_uint(hs_lo[off]);
                }
            }
            #pragma unroll
            for (int mt = 0; mt < 2; mt++)
                #pragma unroll
                for (int nt = 0; nt < 4; nt++) {
                    mma8(d[mt][nt], ahi[mt], bhi[nt]);
                    mma8(d[mt][nt], ahi[mt], blo[nt]);
                    mma8(d[mt][nt], alo[mt], bhi[nt]);
                }
        }
        __syncthreads();
        if (ch + 2 < 16) stage(ch + 2, ch & 1);
    }
    __syncthreads();

    // stage D to smem st[128][72]
    float* st = sm;
    #pragma unroll
    for (int mt = 0; mt < 2; mt++)
        #pragma unroll
        for (int nt = 0; nt < 4; nt++)
            #pragma unroll
            for (int j = 0; j < 4; j++) {
                int m = wm * 32 + mt * 16 + rA + (j >> 1) * 8;
                int n = wn * 32 + nt * 8 + 2 * cA + (j & 1);
                st[m * 72 + n] = d[mt][nt][j];
            }
    __syncthreads();

    float* cv = sm + 128 * 72;
    int*   ci = reinterpret_cast<int*>(cv + 256);
    {
        int b = tid >> 2, q = tid & 3;
        float best = -1e30f; int bi = 0;
        float* op = out + (size_t)b * (TT * VOC) + (size_t)t * VOC + r0 + q * 32;
        #pragma unroll
        for (int g = 0; g < 8; g++) {
            int rb = q * 32 + g * 4;
            float4 v;
            v.x = st[(rb + 0) * 72 + b] + bl[r0 + rb + 0];
            v.y = st[(rb + 1) * 72 + b] + bl[r0 + rb + 1];
            v.z = st[(rb + 2) * 72 + b] + bl[r0 + rb + 2];
            v.w = st[(rb + 3) * 72 + b] + bl[r0 + rb + 3];
            if (v.x > best) { best = v.x; bi = r0 + rb; }
            if (v.y > best) { best = v.y; bi = r0 + rb + 1; }
            if (v.z > best) { best = v.z; bi = r0 + rb + 2; }
            if (v.w > best) { best = v.w; bi = r0 + rb + 3; }
            stcs4(op + g * 4, v);
        }
        cv[tid] = best; ci[tid] = bi;
    }
    __syncthreads();
    if ((tid & 3) == 0) {
        int b = tid >> 2;
        float best = cv[tid]; int bi = ci[tid];
        #pragma unroll
        for (int q = 1; q < 4; q++) {
            float v = cv[tid + q]; int i = ci[tid + q];
            if (v > best || (v == best && i < bi)) { best = v; bi = i; }
        }
        g_pv[blk * 64 + b] = best; g_pi[blk * 64 + b] = bi;
    }
}

// ---------------- kC: argmax finalize (250 partials) ----------------
__global__ __launch_bounds__(512) void kC() {
    if (g_done) return;
    __shared__ float sv[512];
    __shared__ int   si[512];
    __shared__ int   sm2[64];
    int tid = threadIdx.x;
    int b = tid & 63, q = tid >> 6;
    int s = q * 32, e = (s + 32 < NPART) ? s + 32 : NPART;
    float best = -1e30f; int bi = 0x7fffffff;
    for (int k = s; k < e; k++) {
        float v = g_pv[k * 64 + b];
        int   i = g_pi[k * 64 + b];
        if (v > best || (v == best && i < bi)) { best = v; bi = i; }
    }
    sv[q * 64 + b] = best; si[q * 64 + b] = bi;
    __syncthreads();
    if (tid < 64) {
        float bvv = sv[tid]; int bix = si[tid];
        #pragma unroll
        for (int q2 = 1; q2 < 8; q2++) {
            float v = sv[q2 * 64 + tid]; int i = si[q2 * 64 + tid];
            if (v > bvv || (v == bvv && i < bix)) { bvv = v; bix = i; }
        }
        g_word[tid] = bix;
        int m = g_mask[tid] | (bix == END_TOK);
        g_mask[tid] = m;
        sm2[tid] = m;
    }
    __syncthreads();
    if (tid == 0) {
        int all = 1;
        for (int b2 = 0; b2 < 64; b2++) all &= sm2[b2];
        if (all) g_done = 1;
    }
}

extern "C" void kernel_launch(void* const* d_in, const int* in_sizes, int n_in,
                              void* d_out, int out_size) {
    const float* feat = (const float*)d_in[0];
    const float* emb  = (const float*)d_in[1];
    const float* Wih  = (const float*)d_in[2];
    const float* Whh  = (const float*)d_in[3];
    const float* bih  = (const float*)d_in[4];
    const float* bhh  = (const float*)d_in[5];
    const float* Wl   = (const float*)d_in[6];
    const float* bl   = (const float*)d_in[7];
    float* out = (float*)d_out;

    cudaFuncSetAttribute(kBmma,   cudaFuncAttributeMaxDynamicSharedMemorySize, BMMA_SMEM);
    cudaFuncSetAttribute(kGatesM, cudaFuncAttributeMaxDynamicSharedMemorySize, GATES_SMEM);

    kSplitW<<<VOC * HID / 256, 256>>>(Wl);
    kSplitE<<<VOC * HID / 256, 256>>>(emb);
    kSplitG<<<2048 * 1024 / 256, 256>>>(Wih, Whh);
    kInit<<<64, 512>>>(feat);
    for (int t = 0; t < TT; t++) {
        kGatesM<<<dim3(16, 8), 256, GATES_SMEM>>>();
        kPoint<<<64, 512>>>(bih, bhh);
        kBmma<<<NBLK_B, 256, BMMA_SMEM>>>(bl, out, t);
        kC<<<1, 512>>>();
    }
}